// round 1
// baseline (speedup 1.0000x reference)
#include <cuda_runtime.h>
#include <math_constants.h>
#include <cstdint>

// Problem constants
constexpr int C_  = 64;
constexpr int L_  = 720;
constexpr int D_  = 512;
constexpr int P_  = 336;
constexpr int P2_ = 168;
constexpr int H_  = 512;
constexpr int M_  = 64 * 64;   // B*C = 4096 rows

// Tiling
#define BM 128
#define BN 64
#define BKK 16
#define TM 8
#define TN 4
#define NT 256

enum { EPI_GELU = 0, EPI_TANHPI = 1, EPI_AFFINE = 2, EPI_FINAL = 3 };
enum { A_ROW = 0, A_XBSD = 1 };
enum { V_NONE = 0, V_BUF = 1, V_XBSD = 2 };

// Scratch activations (static device memory; no allocation anywhere)
__device__ __align__(128) float g_h[M_ * H_];
__device__ __align__(128) float g_z[M_ * D_];
__device__ __align__(128) float g_x[M_ * L_];
__device__ __align__(128) float g_y[M_ * P_];
__device__ __align__(128) float g_th[M_ * P2_];

__device__ __forceinline__ float gelu_tanh(float x) {
    // jax.nn.gelu default (approximate=True)
    float x3 = x * x * x;
    return 0.5f * x * (1.0f + tanhf(0.7978845608028654f * (x + 0.044715f * x3)));
}

// One generic tiled GEMM with fused epilogues.
//  EPI_GELU   : out = gelu(A@W)                      (ldw = Nlog)
//  EPI_TANHPI : out = pi*tanh(A@W)                   (ldw = Nlog)
//  EPI_AFFINE : out = vin * exp(tanh(A@Ws)) + A@Wt   (W is (K,2*Nlog); s=cols[0,N), t=cols[N,2N))
//  EPI_FINAL  : full rot/koop/scale/koop^-1/rot^-1 + shift epilogue, transposed store
template <int EPI, int ALD, int VSRC, int KDIM>
__global__ __launch_bounds__(NT)
void gemm_k(const float* __restrict__ A, const float* __restrict__ W,
            const float* __restrict__ Vin, float* __restrict__ Out,
            int Nlog, float vscale,
            const float* __restrict__ Theta,
            const float* __restrict__ Ay, const float* __restrict__ By)
{
    constexpr bool PAIR = (EPI == EPI_AFFINE || EPI == EPI_FINAL);

    __shared__ __align__(16) float As[BKK][BM + 4];
    __shared__ __align__(16) float Ws[BKK][BN];
    __shared__ __align__(16) float Wt[BKK][BN];

    const int tid = threadIdx.x;
    const int tx  = tid & 15;   // N direction (16 threads * TN=4 -> 64)
    const int ty  = tid >> 4;   // M direction (16 threads * TM=8 -> 128)
    const int m0  = blockIdx.x * BM;
    const int n0  = blockIdx.y * BN;
    const int ldw = PAIR ? (2 * Nlog) : Nlog;

    float accS[TM][TN];
    float accT[TM][TN];
#pragma unroll
    for (int i = 0; i < TM; i++)
#pragma unroll
        for (int j = 0; j < TN; j++) { accS[i][j] = 0.f; accT[i][j] = 0.f; }

    // W-loader indexing: each thread loads one float4 per W buffer per k-tile
    const int wk = tid >> 4;          // 0..15 = k within tile
    const int wn = (tid & 15) * 4;    // 0..60 = n within tile
    const bool wok = (n0 + wn) < Nlog;  // Nlog is always a multiple of 4

#pragma unroll 1
    for (int kt = 0; kt < KDIM / BKK; ++kt) {
        const int k0 = kt * BKK;

        // ---- load A tile into As[k][m] ----
        if (ALD == A_ROW) {
#pragma unroll
            for (int it = 0; it < 2; ++it) {
                int f  = tid + it * NT;        // 0..511
                int m  = f >> 2;
                int kv = (f & 3) * 4;
                float4 v = *reinterpret_cast<const float4*>(
                    A + (size_t)(m0 + m) * KDIM + k0 + kv);
                As[kv + 0][m] = v.x; As[kv + 1][m] = v.y;
                As[kv + 2][m] = v.z; As[kv + 3][m] = v.w;
            }
        } else {
            // A[m, l] = x_bsd[b, l, c], m = b*64 + c  (coalesced over m)
#pragma unroll
            for (int it = 0; it < 8; ++it) {
                int idx = tid + it * NT;
                int m = idx & (BM - 1);
                int k = idx >> 7;
                int gm = m0 + m;
                As[k][m] = A[(size_t)(gm >> 6) * (L_ * C_) +
                             (size_t)(k0 + k) * C_ + (gm & (C_ - 1))];
            }
        }

        // ---- load W tile(s) ----
        {
            float4 vs = wok ? *reinterpret_cast<const float4*>(
                                  W + (size_t)(k0 + wk) * ldw + n0 + wn)
                            : make_float4(0.f, 0.f, 0.f, 0.f);
            *reinterpret_cast<float4*>(&Ws[wk][wn]) = vs;
            if (PAIR) {
                float4 vt = wok ? *reinterpret_cast<const float4*>(
                                      W + (size_t)(k0 + wk) * ldw + Nlog + n0 + wn)
                                : make_float4(0.f, 0.f, 0.f, 0.f);
                *reinterpret_cast<float4*>(&Wt[wk][wn]) = vt;
            }
        }
        __syncthreads();

        // ---- MAC ----
#pragma unroll
        for (int k = 0; k < BKK; k++) {
            float a[TM], ws[TN], wt[TN];
            *reinterpret_cast<float4*>(&a[0]) =
                *reinterpret_cast<const float4*>(&As[k][ty * TM]);
            *reinterpret_cast<float4*>(&a[4]) =
                *reinterpret_cast<const float4*>(&As[k][ty * TM + 4]);
            *reinterpret_cast<float4*>(&ws[0]) =
                *reinterpret_cast<const float4*>(&Ws[k][tx * TN]);
            if (PAIR)
                *reinterpret_cast<float4*>(&wt[0]) =
                    *reinterpret_cast<const float4*>(&Wt[k][tx * TN]);
#pragma unroll
            for (int i = 0; i < TM; i++)
#pragma unroll
                for (int j = 0; j < TN; j++) {
                    accS[i][j] = fmaf(a[i], ws[j], accS[i][j]);
                    if (PAIR) accT[i][j] = fmaf(a[i], wt[j], accT[i][j]);
                }
        }
        __syncthreads();
    }

    // ---- epilogue ----
#pragma unroll
    for (int i = 0; i < TM; i++) {
        const int gm = m0 + ty * TM + i;
        if (EPI == EPI_FINAL) {
            const int b = gm >> 6, c = gm & (C_ - 1);
#pragma unroll
            for (int jp = 0; jp < TN / 2; jp++) {
                int n = n0 + tx * TN + jp * 2;   // even column -> pair (n, n+1)
                if (n >= Nlog) continue;
                int p = n >> 1;
                float th = Theta[(size_t)gm * P2_ + p];
                float sn, cs;
                sincosf(th, &sn, &cs);
                float av = Ay[c * P2_ + p], bv = By[c * P2_ + p];
                float rn = rsqrtf(av * av + bv * bv);
                float ca = av * rn, cb = bv * rn;
                float yr = Vin[(size_t)gm * P_ + n];
                float yi = Vin[(size_t)gm * P_ + n + 1];
                // rot(theta)
                float r1 = cs * yr - sn * yi, i1 = sn * yr + cs * yi;
                // koop(a,b)
                float r2 = ca * r1 - cb * i1, i2 = cb * r1 + ca * i1;
                // * scale (elementwise on interleaved)
                float sr = expf(tanhf(accS[i][jp * 2]));
                float si = expf(tanhf(accS[i][jp * 2 + 1]));
                float r3 = r2 * sr, i3 = i2 * si;
                // koop inverse
                float r4 = ca * r3 + cb * i3, i4 = -cb * r3 + ca * i3;
                // rot inverse
                float r5 = cs * r4 + sn * i4, i5 = -sn * r4 + cs * i4;
                // + shift, store transposed (B, P, C)
                Out[((size_t)b * P_ + n) * C_ + c]     = r5 + accT[i][jp * 2];
                Out[((size_t)b * P_ + n + 1) * C_ + c] = i5 + accT[i][jp * 2 + 1];
            }
        } else {
#pragma unroll
            for (int j = 0; j < TN; j++) {
                int n = n0 + tx * TN + j;
                if (n >= Nlog) continue;
                float r;
                if (EPI == EPI_GELU) {
                    r = gelu_tanh(accS[i][j]);
                } else if (EPI == EPI_TANHPI) {
                    r = CUDART_PI_F * tanhf(accS[i][j]);
                } else { // EPI_AFFINE
                    float vin;
                    if (VSRC == V_XBSD)
                        vin = Vin[(size_t)(gm >> 6) * (L_ * C_) +
                                  (size_t)n * C_ + (gm & (C_ - 1))];
                    else
                        vin = Vin[(size_t)gm * Nlog + n] * vscale;
                    r = vin * expf(tanhf(accS[i][j])) + accT[i][j];
                }
                Out[(size_t)gm * Nlog + n] = r;
            }
        }
    }
}

extern "C" void kernel_launch(void* const* d_in, const int* in_sizes, int n_in,
                              void* d_out, int out_size)
{
    (void)in_sizes; (void)n_in; (void)out_size;
    const float* x_bsd   = (const float*)d_in[0];
    const float* z0      = (const float*)d_in[1];
    const float* y0      = (const float*)d_in[2];
    const float* W_h     = (const float*)d_in[3];
    const float* W_ssz   = (const float*)d_in[4];
    const float* W_xz_v2 = (const float*)d_in[5];
    const float* W_xz_v3 = (const float*)d_in[6];
    const float* W_xz_v4 = (const float*)d_in[7];
    const float* W_xz_v5 = (const float*)d_in[8];
    const float* W_zx_v0 = (const float*)d_in[9];
    const float* W_zx_v2 = (const float*)d_in[10];
    const float* W_zx_v3 = (const float*)d_in[11];
    // d_in[12] = W_zx_v5: dead code in the reference (x never read after), skipped
    const float* W_zy_v4 = (const float*)d_in[13];
    const float* W_rot   = (const float*)d_in[14];
    const float* W_koo   = (const float*)d_in[15];
    const float* a_y     = (const float*)d_in[16];
    const float* b_y     = (const float*)d_in[17];
    float* out = (float*)d_out;

    float *h, *z, *x, *y, *th;
    cudaGetSymbolAddress((void**)&h,  g_h);
    cudaGetSymbolAddress((void**)&z,  g_z);
    cudaGetSymbolAddress((void**)&x,  g_x);
    cudaGetSymbolAddress((void**)&y,  g_y);
    cudaGetSymbolAddress((void**)&th, g_th);

    const dim3 blk(NT);
    const int MT = M_ / BM;   // 32

    // 1) h = gelu(x^T @ W_h)                      K=720, N=512
    gemm_k<EPI_GELU, A_XBSD, V_NONE, 720><<<dim3(MT, 8), blk>>>(
        x_bsd, W_h, nullptr, h, H_, 1.f, nullptr, nullptr, nullptr);
    // 2) z1 = affine(0.1*z0 ; h @ W_ssz)          K=512, N=512 pairs
    gemm_k<EPI_AFFINE, A_ROW, V_BUF, 512><<<dim3(MT, 8), blk>>>(
        h, W_ssz, z0, z, D_, 0.1f, nullptr, nullptr, nullptr);
    // 3) x1 = affine(x^T ; z1 @ W_zx_v0)          K=512, N=720 pairs
    gemm_k<EPI_AFFINE, A_ROW, V_XBSD, 512><<<dim3(MT, 12), blk>>>(
        z, W_zx_v0, x_bsd, x, L_, 1.f, nullptr, nullptr, nullptr);
    // 4) z2 = affine(z1 ; x1 @ W_xz_v2)           K=720, N=512 pairs
    gemm_k<EPI_AFFINE, A_ROW, V_BUF, 720><<<dim3(MT, 8), blk>>>(
        x, W_xz_v2, z, z, D_, 1.f, nullptr, nullptr, nullptr);
    // 5) x2 = affine(x1 ; z2 @ W_zx_v2)           K=512, N=720 pairs
    gemm_k<EPI_AFFINE, A_ROW, V_BUF, 512><<<dim3(MT, 12), blk>>>(
        z, W_zx_v2, x, x, L_, 1.f, nullptr, nullptr, nullptr);
    // 6) z3 = affine(z2 ; x2 @ W_xz_v3)
    gemm_k<EPI_AFFINE, A_ROW, V_BUF, 720><<<dim3(MT, 8), blk>>>(
        x, W_xz_v3, z, z, D_, 1.f, nullptr, nullptr, nullptr);
    // 7) x3 = affine(x2 ; z3 @ W_zx_v3)
    gemm_k<EPI_AFFINE, A_ROW, V_BUF, 512><<<dim3(MT, 12), blk>>>(
        z, W_zx_v3, x, x, L_, 1.f, nullptr, nullptr, nullptr);
    // 8) z4 = affine(z3 ; x3 @ W_xz_v4)
    gemm_k<EPI_AFFINE, A_ROW, V_BUF, 720><<<dim3(MT, 8), blk>>>(
        x, W_xz_v4, z, z, D_, 1.f, nullptr, nullptr, nullptr);
    // 9) y1 = affine(0.1*y0 ; z4 @ W_zy_v4)       K=512, N=336 pairs
    gemm_k<EPI_AFFINE, A_ROW, V_BUF, 512><<<dim3(MT, 6), blk>>>(
        z, W_zy_v4, y0, y, P_, 0.1f, nullptr, nullptr, nullptr);
    // 10) z5 = affine(z4 ; x3 @ W_xz_v5)
    gemm_k<EPI_AFFINE, A_ROW, V_BUF, 720><<<dim3(MT, 8), blk>>>(
        x, W_xz_v5, z, z, D_, 1.f, nullptr, nullptr, nullptr);
    // (x4 = affine(x3 ; z5 @ W_zx_v5) is dead -> skipped)
    // 11) theta = pi*tanh(z5 @ W_rot)             K=512, N=168
    gemm_k<EPI_TANHPI, A_ROW, V_NONE, 512><<<dim3(MT, 3), blk>>>(
        z, W_rot, nullptr, th, P2_, 1.f, nullptr, nullptr, nullptr);
    // 12) final: z5 @ W_koo -> scale/shift, full rot/koop chain, transposed store
    gemm_k<EPI_FINAL, A_ROW, V_BUF, 512><<<dim3(MT, 6), blk>>>(
        z, W_koo, y, out, P_, 1.f, th, a_y, b_y);
}